// round 5
// baseline (speedup 1.0000x reference)
#include <cuda_runtime.h>
#include <cstdint>

// ---------------------------------------------------------------------------
// VAE decoder: x=concat(motions,angles,z) [4096,2368]
//   L1 (x8 experts): H1[e] = elu(x @ W1[e]^T + b1[e])            [4096,2048]
//   L2: C = sum_e para[e]*elu(H1[e] @ W2[e]^T + b2[e])           [4096,2368]
//   L3: D = elu(concat(C,z) @ W3^T + b3)                         [4096,2048]
//   L4: E = elu(concat(D,z) @ W4^T + b4)                         [4096,2368]
//   L5: out = elu(concat(E,z) @ W5^T + b5)                       [4096,256]
// All GEMMs are A[M,K](row) * W[N,K](row)^T -> C[M,N], K % 32 == 0, M = 4096.
// TF32 mma.sync with fp32 accumulation.
// ---------------------------------------------------------------------------

#define BROWS 4096
#define BM 128
#define BN 128
#define BK 32
#define LDSK 36   // BK + 4 pad -> (36*r + c) % 32 = (4r+c)%32, conflict-free frags

// Scratch (device globals: allocation-free per harness rules)
__device__ float g_X   [(size_t)BROWS * 2368];
__device__ float g_H1  [(size_t)8 * BROWS * 2048];
__device__ float g_bufC[(size_t)BROWS * 2496];   // [:,0:2368]=L2 out, [:,2368:2496]=z
__device__ float g_bufD[(size_t)BROWS * 2176];   // [:,0:2048]=L3 out, tail=z
__device__ float g_bufE[(size_t)BROWS * 2496];   // [:,0:2368]=L4 out, tail=z

__device__ __forceinline__ uint32_t f2tf(float x) {
    uint32_t r; asm("cvt.rna.tf32.f32 %0, %1;" : "=r"(r) : "f"(x)); return r;
}
__device__ __forceinline__ float elu1(float x) {
    return x > 0.f ? x : expm1f(x);
}
__device__ __forceinline__ void mma_tf32(float c[4], const uint32_t a[4], const uint32_t b[2]) {
    asm volatile(
        "mma.sync.aligned.m16n8k8.row.col.f32.tf32.tf32.f32 "
        "{%0,%1,%2,%3}, {%4,%5,%6,%7}, {%8,%9}, {%0,%1,%2,%3};\n"
        : "+f"(c[0]), "+f"(c[1]), "+f"(c[2]), "+f"(c[3])
        : "r"(a[0]), "r"(a[1]), "r"(a[2]), "r"(a[3]), "r"(b[0]), "r"(b[1]));
}

// Build X = concat(motions, angles, z); drop z into the skip tails of C/D/E bufs.
__global__ void pack_kernel(const float* __restrict__ motions,
                            const float* __restrict__ angles,
                            const float* __restrict__ z)
{
    const int total = BROWS * 2752;  // 2368 + 3*128
    for (int i = blockIdx.x * blockDim.x + threadIdx.x; i < total;
         i += gridDim.x * blockDim.x) {
        int b = i / 2752, c = i - b * 2752;
        if (c < 2368) {
            float v;
            if (c < 1792)      v = motions[b * 1792 + c];
            else if (c < 2240) v = angles[b * 448 + (c - 1792)];
            else               v = z[b * 128 + (c - 2240)];
            g_X[(size_t)b * 2368 + c] = v;
        } else {
            int j = c - 2368;
            int which = j >> 7, off = j & 127;
            float v = z[b * 128 + off];
            if (which == 0)      g_bufC[(size_t)b * 2496 + 2368 + off] = v;
            else if (which == 1) g_bufD[(size_t)b * 2176 + 2048 + off] = v;
            else                 g_bufE[(size_t)b * 2496 + 2368 + off] = v;
        }
    }
}

// SUM=false: one GEMM per blockIdx.z (expert-batched or plain); out = elu(AW^T+b)
// SUM=true : loop experts in-register; out = sum_e para[e]*elu(A_e W_e^T + b_e)
template<bool SUM>
__global__ void __launch_bounds__(256, 1)
gemm_elu(const float* __restrict__ A0, int lda, size_t sAe,
         const float* __restrict__ W0, size_t sWe,
         const float* __restrict__ bias0, size_t sBe,
         const float* __restrict__ para,
         float* __restrict__ C0, int ldc, size_t sCe,
         int N, int K, int nexp)
{
    extern __shared__ uint32_t sm[];
    uint32_t* As = sm;                   // [2][BM][LDSK]
    uint32_t* Ws = sm + 2 * BM * LDSK;   // [2][BN][LDSK]

    const int tid = threadIdx.x;
    const int lane = tid & 31, warp = tid >> 5;
    const int warpM = warp & 1, warpN = warp >> 1;   // 2 x 4 warp grid
    const int g = lane >> 2, tg = lane & 3;
    const int mBlock = blockIdx.y * BM;
    const int nBlock = blockIdx.x * BN;
    const int Kiters = K / BK;

    float sum[4][4][4];
    #pragma unroll
    for (int mi = 0; mi < 4; mi++)
        #pragma unroll
        for (int ni = 0; ni < 4; ni++)
            #pragma unroll
            for (int c = 0; c < 4; c++) sum[mi][ni][c] = 0.f;

    const int EBEG = SUM ? 0 : (int)blockIdx.z;
    const int EEND = SUM ? nexp : (int)blockIdx.z + 1;

    float4 ra[4], rw[4];
    float acc[4][4][4];

    for (int e = EBEG; e < EEND; ++e) {
        const float* A = A0 + (size_t)e * sAe;
        const float* W = W0 + (size_t)e * sWe;

        #pragma unroll
        for (int mi = 0; mi < 4; mi++)
            #pragma unroll
            for (int ni = 0; ni < 4; ni++)
                #pragma unroll
                for (int c = 0; c < 4; c++) acc[mi][ni][c] = 0.f;

        auto ldA = [&](int kt) {
            #pragma unroll
            for (int i = 0; i < 4; i++) {
                int idx = tid + i * 256;
                int r = idx >> 3, c4 = idx & 7;
                ra[i] = *reinterpret_cast<const float4*>(
                    A + (size_t)(mBlock + r) * lda + kt * BK + c4 * 4);
            }
        };
        auto ldW = [&](int kt) {
            #pragma unroll
            for (int i = 0; i < 4; i++) {
                int idx = tid + i * 256;
                int r = idx >> 3, c4 = idx & 7;
                int n = nBlock + r;
                if (n < N)
                    rw[i] = *reinterpret_cast<const float4*>(
                        W + (size_t)n * K + kt * BK + c4 * 4);
                else
                    rw[i] = make_float4(0.f, 0.f, 0.f, 0.f);
            }
        };
        auto stA = [&](int buf) {
            uint32_t* S = As + buf * BM * LDSK;
            #pragma unroll
            for (int i = 0; i < 4; i++) {
                int idx = tid + i * 256;
                int r = idx >> 3, c4 = idx & 7;
                uint4 v = make_uint4(f2tf(ra[i].x), f2tf(ra[i].y),
                                     f2tf(ra[i].z), f2tf(ra[i].w));
                *reinterpret_cast<uint4*>(S + r * LDSK + c4 * 4) = v;
            }
        };
        auto stW = [&](int buf) {
            uint32_t* S = Ws + buf * BN * LDSK;
            #pragma unroll
            for (int i = 0; i < 4; i++) {
                int idx = tid + i * 256;
                int r = idx >> 3, c4 = idx & 7;
                uint4 v = make_uint4(f2tf(rw[i].x), f2tf(rw[i].y),
                                     f2tf(rw[i].z), f2tf(rw[i].w));
                *reinterpret_cast<uint4*>(S + r * LDSK + c4 * 4) = v;
            }
        };
        auto comp = [&](int buf) {
            const uint32_t* Ab = As + buf * BM * LDSK + (warpM * 64) * LDSK;
            const uint32_t* Wb = Ws + buf * BN * LDSK + (warpN * 32) * LDSK;
            #pragma unroll
            for (int ks = 0; ks < 4; ks++) {
                uint32_t af[4][4], bf[4][2];
                const int kc = ks * 8 + tg;
                #pragma unroll
                for (int mi = 0; mi < 4; mi++) {
                    const uint32_t* p = Ab + (mi * 16 + g) * LDSK + kc;
                    af[mi][0] = p[0];
                    af[mi][1] = p[8 * LDSK];
                    af[mi][2] = p[4];
                    af[mi][3] = p[8 * LDSK + 4];
                }
                #pragma unroll
                for (int ni = 0; ni < 4; ni++) {
                    const uint32_t* p = Wb + (ni * 8 + g) * LDSK + kc;
                    bf[ni][0] = p[0];
                    bf[ni][1] = p[4];
                }
                #pragma unroll
                for (int mi = 0; mi < 4; mi++)
                    #pragma unroll
                    for (int ni = 0; ni < 4; ni++)
                        mma_tf32(acc[mi][ni], af[mi], bf[ni]);
            }
        };

        // Double-buffered mainloop
        ldA(0); ldW(0); stA(0); stW(0);
        for (int kt = 0; kt < Kiters; kt++) {
            __syncthreads();
            int cur = kt & 1;
            bool more = (kt + 1 < Kiters);
            if (more) { ldA(kt + 1); ldW(kt + 1); }
            comp(cur);
            if (more) { stA(1 - cur); stW(1 - cur); }
        }
        __syncthreads();  // protect buffer 0 reuse across experts

        // Fold: bias + ELU (+ para-weighted sum for SUM path; pe=1 otherwise)
        const float* bias = bias0 + (size_t)e * sBe;
        float pe = SUM ? para[e] : 1.0f;
        #pragma unroll
        for (int ni = 0; ni < 4; ni++) {
            int col0 = nBlock + warpN * 32 + ni * 8 + tg * 2;
            float b0 = (col0 < N)     ? bias[col0]     : 0.f;
            float b1 = (col0 + 1 < N) ? bias[col0 + 1] : 0.f;
            #pragma unroll
            for (int mi = 0; mi < 4; mi++) {
                sum[mi][ni][0] += pe * elu1(acc[mi][ni][0] + b0);
                sum[mi][ni][1] += pe * elu1(acc[mi][ni][1] + b1);
                sum[mi][ni][2] += pe * elu1(acc[mi][ni][2] + b0);
                sum[mi][ni][3] += pe * elu1(acc[mi][ni][3] + b1);
            }
        }
    }

    // Store (float2 = adjacent cols; N is always even)
    float* C = C0 + (SUM ? (size_t)0 : (size_t)blockIdx.z * sCe);
    #pragma unroll
    for (int mi = 0; mi < 4; mi++) {
        #pragma unroll
        for (int ni = 0; ni < 4; ni++) {
            int col0 = nBlock + warpN * 32 + ni * 8 + tg * 2;
            if (col0 >= N) continue;
            int r0 = mBlock + warpM * 64 + mi * 16 + g;
            *reinterpret_cast<float2*>(C + (size_t)r0 * ldc + col0) =
                make_float2(sum[mi][ni][0], sum[mi][ni][1]);
            *reinterpret_cast<float2*>(C + (size_t)(r0 + 8) * ldc + col0) =
                make_float2(sum[mi][ni][2], sum[mi][ni][3]);
        }
    }
}

extern "C" void kernel_launch(void* const* d_in, const int* in_sizes, int n_in,
                              void* d_out, int out_size)
{
    const float* motions = (const float*)d_in[0];
    const float* angles  = (const float*)d_in[1];
    const float* z       = (const float*)d_in[2];
    const float* l1_w    = (const float*)d_in[3];
    const float* l1_b    = (const float*)d_in[4];
    const float* l2_w    = (const float*)d_in[5];
    const float* l2_b    = (const float*)d_in[6];
    const float* para    = (const float*)d_in[7];
    const float* l3_w    = (const float*)d_in[8];
    const float* l3_b    = (const float*)d_in[9];
    const float* l4_w    = (const float*)d_in[10];
    const float* l4_b    = (const float*)d_in[11];
    const float* l5_w    = (const float*)d_in[12];
    const float* l5_b    = (const float*)d_in[13];
    float* out = (float*)d_out;

    float *X, *H1, *bufC, *bufD, *bufE;
    cudaGetSymbolAddress((void**)&X,    g_X);
    cudaGetSymbolAddress((void**)&H1,   g_H1);
    cudaGetSymbolAddress((void**)&bufC, g_bufC);
    cudaGetSymbolAddress((void**)&bufD, g_bufD);
    cudaGetSymbolAddress((void**)&bufE, g_bufE);

    const size_t shmem = (size_t)4 * 128 * LDSK * sizeof(uint32_t);  // 73728 B
    cudaFuncSetAttribute(gemm_elu<false>,
                         cudaFuncAttributeMaxDynamicSharedMemorySize, (int)shmem);
    cudaFuncSetAttribute(gemm_elu<true>,
                         cudaFuncAttributeMaxDynamicSharedMemorySize, (int)shmem);

    pack_kernel<<<4096, 256>>>(motions, angles, z);

    // L1: H1[e] = elu(X @ W1[e]^T + b1[e]); batched over gridDim.z
    gemm_elu<false><<<dim3(2048 / BN, BROWS / BM, 8), 256, shmem>>>(
        X, 2368, (size_t)0,
        l1_w, (size_t)2048 * 2368,
        l1_b, (size_t)2048,
        nullptr,
        H1, 2048, (size_t)BROWS * 2048,
        2048, 2368, 1);

    // L2: bufC[:, :2368] = sum_e para[e]*elu(H1[e] @ W2[e]^T + b2[e])
    gemm_elu<true><<<dim3((2368 + BN - 1) / BN, BROWS / BM, 1), 256, shmem>>>(
        H1, 2048, (size_t)BROWS * 2048,
        l2_w, (size_t)2368 * 2048,
        l2_b, (size_t)2368,
        para,
        bufC, 2496, (size_t)0,
        2368, 2048, 8);

    // L3: bufD[:, :2048] = elu(bufC @ W3^T + b3), K=2496
    gemm_elu<false><<<dim3(2048 / BN, BROWS / BM, 1), 256, shmem>>>(
        bufC, 2496, (size_t)0,
        l3_w, (size_t)0,
        l3_b, (size_t)0,
        nullptr,
        bufD, 2176, (size_t)0,
        2048, 2496, 1);

    // L4: bufE[:, :2368] = elu(bufD @ W4^T + b4), K=2176
    gemm_elu<false><<<dim3((2368 + BN - 1) / BN, BROWS / BM, 1), 256, shmem>>>(
        bufD, 2176, (size_t)0,
        l4_w, (size_t)0,
        l4_b, (size_t)0,
        nullptr,
        bufE, 2496, (size_t)0,
        2368, 2176, 1);

    // L5: out = elu(bufE @ W5^T + b5), K=2496
    gemm_elu<false><<<dim3(256 / BN, BROWS / BM, 1), 256, shmem>>>(
        bufE, 2496, (size_t)0,
        l5_w, (size_t)0,
        l5_b, (size_t)0,
        nullptr,
        out, 256, (size_t)0,
        256, 2496, 1);
}

// round 6
// speedup vs baseline: 1.0082x; 1.0082x over previous
#include <cuda_runtime.h>
#include <cstdint>

// ---------------------------------------------------------------------------
// VAE decoder: x=concat(motions,angles,z) [4096,2368]
//   L1 (x8 experts): H1[e] = elu(x @ W1[e]^T + b1[e])            [4096,2048]
//   L2: C = sum_e para[e]*elu(H1[e] @ W2[e]^T + b2[e])           [4096,2368]
//   L3: D = elu(concat(C,z) @ W3^T + b3)                         [4096,2048]
//   L4: E = elu(concat(D,z) @ W4^T + b4)                         [4096,2368]
//   L5: out = elu(concat(E,z) @ W5^T + b5)                       [4096,256]
// All GEMMs are A[M,K](row) * W[N,K](row)^T -> C[M,N], K % 32 == 0, M = 4096.
// TF32 mma.sync with fp32 accumulation.
// ---------------------------------------------------------------------------

#define BROWS 4096
#define BM 128
#define BN 128
#define BK 32
#define LDSK 36   // BK + 4 pad -> (36*r + c) % 32 = (4r+c)%32, conflict-free frags

// Scratch (device globals: allocation-free per harness rules)
__device__ float g_X   [(size_t)BROWS * 2368];
__device__ float g_H1  [(size_t)8 * BROWS * 2048];
__device__ float g_bufC[(size_t)BROWS * 2496];   // [:,0:2368]=L2 out, [:,2368:2496]=z
__device__ float g_bufD[(size_t)BROWS * 2176];   // [:,0:2048]=L3 out, tail=z
__device__ float g_bufE[(size_t)BROWS * 2496];   // [:,0:2368]=L4 out, tail=z

__device__ __forceinline__ uint32_t f2tf(float x) {
    uint32_t r; asm("cvt.rna.tf32.f32 %0, %1;" : "=r"(r) : "f"(x)); return r;
}
__device__ __forceinline__ float elu1(float x) {
    return x > 0.f ? x : expm1f(x);
}
__device__ __forceinline__ void mma_tf32(float c[4], const uint32_t a[4], const uint32_t b[2]) {
    asm volatile(
        "mma.sync.aligned.m16n8k8.row.col.f32.tf32.tf32.f32 "
        "{%0,%1,%2,%3}, {%4,%5,%6,%7}, {%8,%9}, {%0,%1,%2,%3};\n"
        : "+f"(c[0]), "+f"(c[1]), "+f"(c[2]), "+f"(c[3])
        : "r"(a[0]), "r"(a[1]), "r"(a[2]), "r"(a[3]), "r"(b[0]), "r"(b[1]));
}

// Build X = concat(motions, angles, z); drop z into the skip tails of C/D/E bufs.
__global__ void pack_kernel(const float* __restrict__ motions,
                            const float* __restrict__ angles,
                            const float* __restrict__ z)
{
    const int total = BROWS * 2752;  // 2368 + 3*128
    for (int i = blockIdx.x * blockDim.x + threadIdx.x; i < total;
         i += gridDim.x * blockDim.x) {
        int b = i / 2752, c = i - b * 2752;
        if (c < 2368) {
            float v;
            if (c < 1792)      v = motions[b * 1792 + c];
            else if (c < 2240) v = angles[b * 448 + (c - 1792)];
            else               v = z[b * 128 + (c - 2240)];
            g_X[(size_t)b * 2368 + c] = v;
        } else {
            int j = c - 2368;
            int which = j >> 7, off = j & 127;
            float v = z[b * 128 + off];
            if (which == 0)      g_bufC[(size_t)b * 2496 + 2368 + off] = v;
            else if (which == 1) g_bufD[(size_t)b * 2176 + 2048 + off] = v;
            else                 g_bufE[(size_t)b * 2496 + 2368 + off] = v;
        }
    }
}

// SUM=false: one GEMM per blockIdx.z (expert-batched or plain); out = elu(AW^T+b)
// SUM=true : loop experts in-register; out = sum_e para[e]*elu(A_e W_e^T + b_e)
template<bool SUM>
__global__ void __launch_bounds__(256, 1)
gemm_elu(const float* __restrict__ A0, int lda, size_t sAe,
         const float* __restrict__ W0, size_t sWe,
         const float* __restrict__ bias0, size_t sBe,
         const float* __restrict__ para,
         float* __restrict__ C0, int ldc, size_t sCe,
         int N, int K, int nexp)
{
    extern __shared__ uint32_t sm[];
    uint32_t* As = sm;                   // [2][BM][LDSK]
    uint32_t* Ws = sm + 2 * BM * LDSK;   // [2][BN][LDSK]

    const int tid = threadIdx.x;
    const int lane = tid & 31, warp = tid >> 5;
    const int warpM = warp & 1, warpN = warp >> 1;   // 2 x 4 warp grid
    const int g = lane >> 2, tg = lane & 3;
    const int mBlock = blockIdx.y * BM;
    const int nBlock = blockIdx.x * BN;
    const int Kiters = K / BK;

    float sum[4][4][4];
    #pragma unroll
    for (int mi = 0; mi < 4; mi++)
        #pragma unroll
        for (int ni = 0; ni < 4; ni++)
            #pragma unroll
            for (int c = 0; c < 4; c++) sum[mi][ni][c] = 0.f;

    const int EBEG = SUM ? 0 : (int)blockIdx.z;
    const int EEND = SUM ? nexp : (int)blockIdx.z + 1;

    float4 ra[4], rw[4];
    float acc[4][4][4];

    for (int e = EBEG; e < EEND; ++e) {
        const float* A = A0 + (size_t)e * sAe;
        const float* W = W0 + (size_t)e * sWe;

        #pragma unroll
        for (int mi = 0; mi < 4; mi++)
            #pragma unroll
            for (int ni = 0; ni < 4; ni++)
                #pragma unroll
                for (int c = 0; c < 4; c++) acc[mi][ni][c] = 0.f;

        auto ldA = [&](int kt) {
            #pragma unroll
            for (int i = 0; i < 4; i++) {
                int idx = tid + i * 256;
                int r = idx >> 3, c4 = idx & 7;
                ra[i] = *reinterpret_cast<const float4*>(
                    A + (size_t)(mBlock + r) * lda + kt * BK + c4 * 4);
            }
        };
        auto ldW = [&](int kt) {
            #pragma unroll
            for (int i = 0; i < 4; i++) {
                int idx = tid + i * 256;
                int r = idx >> 3, c4 = idx & 7;
                int n = nBlock + r;
                if (n < N)
                    rw[i] = *reinterpret_cast<const float4*>(
                        W + (size_t)n * K + kt * BK + c4 * 4);
                else
                    rw[i] = make_float4(0.f, 0.f, 0.f, 0.f);
            }
        };
        auto stA = [&](int buf) {
            uint32_t* S = As + buf * BM * LDSK;
            #pragma unroll
            for (int i = 0; i < 4; i++) {
                int idx = tid + i * 256;
                int r = idx >> 3, c4 = idx & 7;
                uint4 v = make_uint4(f2tf(ra[i].x), f2tf(ra[i].y),
                                     f2tf(ra[i].z), f2tf(ra[i].w));
                *reinterpret_cast<uint4*>(S + r * LDSK + c4 * 4) = v;
            }
        };
        auto stW = [&](int buf) {
            uint32_t* S = Ws + buf * BN * LDSK;
            #pragma unroll
            for (int i = 0; i < 4; i++) {
                int idx = tid + i * 256;
                int r = idx >> 3, c4 = idx & 7;
                uint4 v = make_uint4(f2tf(rw[i].x), f2tf(rw[i].y),
                                     f2tf(rw[i].z), f2tf(rw[i].w));
                *reinterpret_cast<uint4*>(S + r * LDSK + c4 * 4) = v;
            }
        };
        auto comp = [&](int buf) {
            const uint32_t* Ab = As + buf * BM * LDSK + (warpM * 64) * LDSK;
            const uint32_t* Wb = Ws + buf * BN * LDSK + (warpN * 32) * LDSK;
            #pragma unroll
            for (int ks = 0; ks < 4; ks++) {
                uint32_t af[4][4], bf[4][2];
                const int kc = ks * 8 + tg;
                #pragma unroll
                for (int mi = 0; mi < 4; mi++) {
                    const uint32_t* p = Ab + (mi * 16 + g) * LDSK + kc;
                    af[mi][0] = p[0];
                    af[mi][1] = p[8 * LDSK];
                    af[mi][2] = p[4];
                    af[mi][3] = p[8 * LDSK + 4];
                }
                #pragma unroll
                for (int ni = 0; ni < 4; ni++) {
                    const uint32_t* p = Wb + (ni * 8 + g) * LDSK + kc;
                    bf[ni][0] = p[0];
                    bf[ni][1] = p[4];
                }
                #pragma unroll
                for (int mi = 0; mi < 4; mi++)
                    #pragma unroll
                    for (int ni = 0; ni < 4; ni++)
                        mma_tf32(acc[mi][ni], af[mi], bf[ni]);
            }
        };

        // Double-buffered mainloop
        ldA(0); ldW(0); stA(0); stW(0);
        for (int kt = 0; kt < Kiters; kt++) {
            __syncthreads();
            int cur = kt & 1;
            bool more = (kt + 1 < Kiters);
            if (more) { ldA(kt + 1); ldW(kt + 1); }
            comp(cur);
            if (more) { stA(1 - cur); stW(1 - cur); }
        }
        __syncthreads();  // protect buffer 0 reuse across experts

        // Fold: bias + ELU (+ para-weighted sum for SUM path; pe=1 otherwise)
        const float* bias = bias0 + (size_t)e * sBe;
        float pe = SUM ? para[e] : 1.0f;
        #pragma unroll
        for (int ni = 0; ni < 4; ni++) {
            int col0 = nBlock + warpN * 32 + ni * 8 + tg * 2;
            float b0 = (col0 < N)     ? bias[col0]     : 0.f;
            float b1 = (col0 + 1 < N) ? bias[col0 + 1] : 0.f;
            #pragma unroll
            for (int mi = 0; mi < 4; mi++) {
                sum[mi][ni][0] += pe * elu1(acc[mi][ni][0] + b0);
                sum[mi][ni][1] += pe * elu1(acc[mi][ni][1] + b1);
                sum[mi][ni][2] += pe * elu1(acc[mi][ni][2] + b0);
                sum[mi][ni][3] += pe * elu1(acc[mi][ni][3] + b1);
            }
        }
    }

    // Store (float2 = adjacent cols; N is always even)
    float* C = C0 + (SUM ? (size_t)0 : (size_t)blockIdx.z * sCe);
    #pragma unroll
    for (int mi = 0; mi < 4; mi++) {
        #pragma unroll
        for (int ni = 0; ni < 4; ni++) {
            int col0 = nBlock + warpN * 32 + ni * 8 + tg * 2;
            if (col0 >= N) continue;
            int r0 = mBlock + warpM * 64 + mi * 16 + g;
            *reinterpret_cast<float2*>(C + (size_t)r0 * ldc + col0) =
                make_float2(sum[mi][ni][0], sum[mi][ni][1]);
            *reinterpret_cast<float2*>(C + (size_t)(r0 + 8) * ldc + col0) =
                make_float2(sum[mi][ni][2], sum[mi][ni][3]);
        }
    }
}

extern "C" void kernel_launch(void* const* d_in, const int* in_sizes, int n_in,
                              void* d_out, int out_size)
{
    const float* motions = (const float*)d_in[0];
    const float* angles  = (const float*)d_in[1];
    const float* z       = (const float*)d_in[2];
    const float* l1_w    = (const float*)d_in[3];
    const float* l1_b    = (const float*)d_in[4];
    const float* l2_w    = (const float*)d_in[5];
    const float* l2_b    = (const float*)d_in[6];
    const float* para    = (const float*)d_in[7];
    const float* l3_w    = (const float*)d_in[8];
    const float* l3_b    = (const float*)d_in[9];
    const float* l4_w    = (const float*)d_in[10];
    const float* l4_b    = (const float*)d_in[11];
    const float* l5_w    = (const float*)d_in[12];
    const float* l5_b    = (const float*)d_in[13];
    float* out = (float*)d_out;

    float *X, *H1, *bufC, *bufD, *bufE;
    cudaGetSymbolAddress((void**)&X,    g_X);
    cudaGetSymbolAddress((void**)&H1,   g_H1);
    cudaGetSymbolAddress((void**)&bufC, g_bufC);
    cudaGetSymbolAddress((void**)&bufD, g_bufD);
    cudaGetSymbolAddress((void**)&bufE, g_bufE);

    const size_t shmem = (size_t)4 * 128 * LDSK * sizeof(uint32_t);  // 73728 B
    cudaFuncSetAttribute(gemm_elu<false>,
                         cudaFuncAttributeMaxDynamicSharedMemorySize, (int)shmem);
    cudaFuncSetAttribute(gemm_elu<true>,
                         cudaFuncAttributeMaxDynamicSharedMemorySize, (int)shmem);

    pack_kernel<<<4096, 256>>>(motions, angles, z);

    // L1: H1[e] = elu(X @ W1[e]^T + b1[e]); batched over gridDim.z
    gemm_elu<false><<<dim3(2048 / BN, BROWS / BM, 8), 256, shmem>>>(
        X, 2368, (size_t)0,
        l1_w, (size_t)2048 * 2368,
        l1_b, (size_t)2048,
        nullptr,
        H1, 2048, (size_t)BROWS * 2048,
        2048, 2368, 1);

    // L2: bufC[:, :2368] = sum_e para[e]*elu(H1[e] @ W2[e]^T + b2[e])
    gemm_elu<true><<<dim3((2368 + BN - 1) / BN, BROWS / BM, 1), 256, shmem>>>(
        H1, 2048, (size_t)BROWS * 2048,
        l2_w, (size_t)2368 * 2048,
        l2_b, (size_t)2368,
        para,
        bufC, 2496, (size_t)0,
        2368, 2048, 8);

    // L3: bufD[:, :2048] = elu(bufC @ W3^T + b3), K=2496
    gemm_elu<false><<<dim3(2048 / BN, BROWS / BM, 1), 256, shmem>>>(
        bufC, 2496, (size_t)0,
        l3_w, (size_t)0,
        l3_b, (size_t)0,
        nullptr,
        bufD, 2176, (size_t)0,
        2048, 2496, 1);

    // L4: bufE[:, :2368] = elu(bufD @ W4^T + b4), K=2176
    gemm_elu<false><<<dim3((2368 + BN - 1) / BN, BROWS / BM, 1), 256, shmem>>>(
        bufD, 2176, (size_t)0,
        l4_w, (size_t)0,
        l4_b, (size_t)0,
        nullptr,
        bufE, 2496, (size_t)0,
        2368, 2176, 1);

    // L5: out = elu(bufE @ W5^T + b5), K=2496
    gemm_elu<false><<<dim3(256 / BN, BROWS / BM, 1), 256, shmem>>>(
        bufE, 2496, (size_t)0,
        l5_w, (size_t)0,
        l5_b, (size_t)0,
        nullptr,
        out, 256, (size_t)0,
        256, 2496, 1);
}

// round 9
// speedup vs baseline: 1.1999x; 1.1901x over previous
#include <cuda_runtime.h>
#include <cstdint>

// ===========================================================================
// VAE decoder, sm_103 fallback tensor path (mma.sync m16n8k8 tf32).
// All operands pre-rounded to tf32 in GMEM; GEMM mainloop is a 3-stage
// cp.async pipeline with zero conversion work. 2 CTAs/SM.
// GEMMs: A[M,K] row * W[N,K] row^T -> C[M,N], M=4096, K%32==0.
// ===========================================================================

#define BROWS 4096
#define BM 128
#define BN 128
#define BK 32
#define LDSK 36            // pad: bank = (4r+c)%32 -> conflict-free frag loads
#define STAGES 3
#define STG_FLT (2 * BM * LDSK)        // floats per stage (A + W) = 9216
#define STG_BYTES (STG_FLT * 4)        // 36864

// ---- scratch (device globals; allocation-free) ----------------------------
__device__ float g_X  [(size_t)BROWS * 2368];            // tf32
__device__ float g_H1 [(size_t)8 * BROWS * 2048];        // tf32
__device__ float g_W1c[(size_t)8 * 2048 * 2368];         // tf32
__device__ float g_W2c[(size_t)8 * 2432 * 2048];         // tf32, N padded
__device__ float g_W3c[(size_t)2048 * 2496];
__device__ float g_W4c[(size_t)2432 * 2176];             // N padded
__device__ float g_W5c[(size_t)256 * 2496];
__device__ float g_bufC[(size_t)BROWS * 2496];           // L2 sum + z tail
__device__ float g_bufD[(size_t)BROWS * 2176];           // L3 out + z tail
__device__ float g_bufE[(size_t)BROWS * 2496];           // L4 out + z tail
__device__ float g_E2 [(size_t)8 * BROWS * 2368];        // per-expert L2 (fp32)

// ---- helpers --------------------------------------------------------------
__device__ __forceinline__ uint32_t f2tf(float x) {
    uint32_t r; asm("cvt.rna.tf32.f32 %0, %1;" : "=r"(r) : "f"(x)); return r;
}
__device__ __forceinline__ float tfr(float x) { return __uint_as_float(f2tf(x)); }
__device__ __forceinline__ float elu1(float x) { return x > 0.f ? x : expm1f(x); }
__device__ __forceinline__ uint32_t smem_u32(const void* p) {
    uint32_t a;
    asm("{ .reg .u64 t; cvta.to.shared.u64 t, %1; cvt.u32.u64 %0, t; }" : "=r"(a) : "l"(p));
    return a;
}
__device__ __forceinline__ void cp16(uint32_t d, const void* s) {
    asm volatile("cp.async.cg.shared.global [%0], [%1], 16;" :: "r"(d), "l"(s) : "memory");
}
__device__ __forceinline__ void cp_commit() {
    asm volatile("cp.async.commit_group;" ::: "memory");
}
__device__ __forceinline__ void cp_wait1() {
    asm volatile("cp.async.wait_group 1;" ::: "memory");
}
__device__ __forceinline__ void mma_tf32(float c[4], const uint32_t a[4], const uint32_t b[2]) {
    asm volatile(
        "mma.sync.aligned.m16n8k8.row.col.f32.tf32.tf32.f32 "
        "{%0,%1,%2,%3}, {%4,%5,%6,%7}, {%8,%9}, {%0,%1,%2,%3};\n"
        : "+f"(c[0]), "+f"(c[1]), "+f"(c[2]), "+f"(c[3])
        : "r"(a[0]), "r"(a[1]), "r"(a[2]), "r"(a[3]), "r"(b[0]), "r"(b[1]));
}

// ---- prep kernels ---------------------------------------------------------
// Weights: [E][N][K] fp32 -> [E][Npad][K] tf32 (zero rows >= N)
__global__ void cvt_pad(const float* __restrict__ src, float* __restrict__ dst,
                        int N, int K, int Npad, long long total)
{
    for (long long i = (long long)blockIdx.x * blockDim.x + threadIdx.x; i < total;
         i += (long long)gridDim.x * blockDim.x) {
        int k = (int)(i % K);
        long long t = i / K;
        int row = (int)(t % Npad);
        int e = (int)(t / Npad);
        dst[i] = (row < N) ? tfr(src[((size_t)e * N + row) * K + k]) : 0.f;
    }
}

// X = tf32(concat(motions, angles, z)); z tails into bufC/D/E (tf32).
__global__ void pack_kernel(const float* __restrict__ motions,
                            const float* __restrict__ angles,
                            const float* __restrict__ z)
{
    const int total = BROWS * 2752;
    for (int i = blockIdx.x * blockDim.x + threadIdx.x; i < total;
         i += gridDim.x * blockDim.x) {
        int b = i / 2752, c = i - b * 2752;
        if (c < 2368) {
            float v;
            if (c < 1792)      v = motions[b * 1792 + c];
            else if (c < 2240) v = angles[b * 448 + (c - 1792)];
            else               v = z[b * 128 + (c - 2240)];
            g_X[(size_t)b * 2368 + c] = tfr(v);
        } else {
            int j = c - 2368;
            int which = j >> 7, off = j & 127;
            float v = tfr(z[b * 128 + off]);
            if (which == 0)      g_bufC[(size_t)b * 2496 + 2368 + off] = v;
            else if (which == 1) g_bufD[(size_t)b * 2176 + 2048 + off] = v;
            else                 g_bufE[(size_t)b * 2496 + 2368 + off] = v;
        }
    }
}

// bufC[:, :2368] = tf32( sum_e E2[e] )
__global__ void reduce_kernel()
{
    const int total = BROWS * (2368 / 4);
    for (int i = blockIdx.x * blockDim.x + threadIdx.x; i < total;
         i += gridDim.x * blockDim.x) {
        int b = i / 592;
        int c = (i - b * 592) * 4;
        float4 s = make_float4(0.f, 0.f, 0.f, 0.f);
        #pragma unroll
        for (int e = 0; e < 8; e++) {
            float4 v = *(const float4*)&g_E2[((size_t)e * BROWS + b) * 2368 + c];
            s.x += v.x; s.y += v.y; s.z += v.z; s.w += v.w;
        }
        *(float4*)&g_bufC[(size_t)b * 2496 + c] =
            make_float4(tfr(s.x), tfr(s.y), tfr(s.z), tfr(s.w));
    }
}

// ---- pipelined GEMM -------------------------------------------------------
// ROUND: tf32-round the output (feeds a later GEMM). PARA: scale by para[e].
template<bool ROUND, bool PARA>
__global__ void __launch_bounds__(256, 2)
gemm_pipe(const float* __restrict__ A0, int lda, size_t sAe,
          const float* __restrict__ W0, size_t sWe,
          const float* __restrict__ bias0, int sBe,
          const float* __restrict__ para,
          float* __restrict__ C0, int ldc, size_t sCe,
          int N, int K)
{
    extern __shared__ float smem[];
    const uint32_t sbase = smem_u32(smem);

    const int tid = threadIdx.x;
    const int lane = tid & 31, warp = tid >> 5;
    const int warpM = warp & 1, warpN = warp >> 1;       // 2 x 4 warps
    const int g = lane >> 2, tg = lane & 3;
    const int mBlock = blockIdx.y * BM;
    const int nBlock = blockIdx.x * BN;
    const int e = blockIdx.z;
    const int Kiters = K / BK;

    const float* A = A0 + (size_t)e * sAe;
    const float* W = W0 + (size_t)e * sWe;

    // per-thread copy coords: 8 chunks of 16B per 128-row operand, 4/thread
    const int cr = tid >> 3;          // row (0..127), +128 rows via i*32
    const int cc = (tid & 7) * 16;    // byte offset within row (0..112)

    auto issue = [&](int stage, int kt) {
        uint32_t sa = sbase + stage * STG_BYTES;
        const float* Ag = A + (size_t)cr * lda + kt * BK + (cc >> 2);
        const float* Wg = W + (size_t)(nBlock + cr) * K + kt * BK + (cc >> 2);
        #pragma unroll
        for (int i = 0; i < 4; i++) {
            int r = cr + i * 32;
            cp16(sa + (uint32_t)(r * (LDSK * 4)) + cc,
                 A + (size_t)(mBlock + r) * lda + kt * BK + (cc >> 2));
        }
        uint32_t sw = sa + BM * LDSK * 4;
        #pragma unroll
        for (int i = 0; i < 4; i++) {
            int r = cr + i * 32;
            cp16(sw + (uint32_t)(r * (LDSK * 4)) + cc,
                 W + (size_t)(nBlock + r) * K + kt * BK + (cc >> 2));
        }
        (void)Ag; (void)Wg;
    };

    float acc[4][4][4];
    #pragma unroll
    for (int mi = 0; mi < 4; mi++)
        #pragma unroll
        for (int ni = 0; ni < 4; ni++)
            #pragma unroll
            for (int c = 0; c < 4; c++) acc[mi][ni][c] = 0.f;

    // prologue: stages 0..STAGES-2
    #pragma unroll
    for (int s = 0; s < STAGES - 1; s++) {
        if (s < Kiters) issue(s, s);
        cp_commit();
    }

    const uint32_t* Asm = (const uint32_t*)smem;
    for (int kt = 0; kt < Kiters; kt++) {
        cp_wait1();
        __syncthreads();

        int nxt = kt + STAGES - 1;
        if (nxt < Kiters) issue(nxt % STAGES, nxt);
        cp_commit();

        const int st = kt % STAGES;
        const uint32_t* Ab = Asm + st * STG_FLT + (warpM * 64) * LDSK;
        const uint32_t* Wb = Asm + st * STG_FLT + BM * LDSK + (warpN * 32) * LDSK;
        #pragma unroll
        for (int ks = 0; ks < 4; ks++) {
            uint32_t af[4][4], bf[4][2];
            const int kc = ks * 8 + tg;
            #pragma unroll
            for (int mi = 0; mi < 4; mi++) {
                const uint32_t* p = Ab + (mi * 16 + g) * LDSK + kc;
                af[mi][0] = p[0];
                af[mi][1] = p[8 * LDSK];
                af[mi][2] = p[4];
                af[mi][3] = p[8 * LDSK + 4];
            }
            #pragma unroll
            for (int ni = 0; ni < 4; ni++) {
                const uint32_t* p = Wb + (ni * 8 + g) * LDSK + kc;
                bf[ni][0] = p[0];
                bf[ni][1] = p[4];
            }
            #pragma unroll
            for (int mi = 0; mi < 4; mi++)
                #pragma unroll
                for (int ni = 0; ni < 4; ni++)
                    mma_tf32(acc[mi][ni], af[mi], bf[ni]);
        }
    }

    // epilogue: bias + ELU (+ para, + tf32 round), guarded store
    const float* bias = bias0 + (size_t)e * sBe;
    const float pe = PARA ? para[e] : 1.0f;
    float* C = C0 + (size_t)e * sCe;
    #pragma unroll
    for (int ni = 0; ni < 4; ni++) {
        int col0 = nBlock + warpN * 32 + ni * 8 + tg * 2;
        if (col0 >= N) continue;
        float b0 = bias[col0];
        float b1 = bias[col0 + 1];
        #pragma unroll
        for (int mi = 0; mi < 4; mi++) {
            int r0 = mBlock + warpM * 64 + mi * 16 + g;
            float y0 = elu1(acc[mi][ni][0] + b0) * pe;
            float y1 = elu1(acc[mi][ni][1] + b1) * pe;
            float y2 = elu1(acc[mi][ni][2] + b0) * pe;
            float y3 = elu1(acc[mi][ni][3] + b1) * pe;
            if (ROUND) { y0 = tfr(y0); y1 = tfr(y1); y2 = tfr(y2); y3 = tfr(y3); }
            *reinterpret_cast<float2*>(C + (size_t)r0 * ldc + col0) = make_float2(y0, y1);
            *reinterpret_cast<float2*>(C + (size_t)(r0 + 8) * ldc + col0) = make_float2(y2, y3);
        }
    }
}

// ---- launch ---------------------------------------------------------------
extern "C" void kernel_launch(void* const* d_in, const int* in_sizes, int n_in,
                              void* d_out, int out_size)
{
    const float* motions = (const float*)d_in[0];
    const float* angles  = (const float*)d_in[1];
    const float* z       = (const float*)d_in[2];
    const float* l1_w    = (const float*)d_in[3];
    const float* l1_b    = (const float*)d_in[4];
    const float* l2_w    = (const float*)d_in[5];
    const float* l2_b    = (const float*)d_in[6];
    const float* para    = (const float*)d_in[7];
    const float* l3_w    = (const float*)d_in[8];
    const float* l3_b    = (const float*)d_in[9];
    const float* l4_w    = (const float*)d_in[10];
    const float* l4_b    = (const float*)d_in[11];
    const float* l5_w    = (const float*)d_in[12];
    const float* l5_b    = (const float*)d_in[13];
    float* out = (float*)d_out;

    float *X, *H1, *W1c, *W2c, *W3c, *W4c, *W5c, *bufC, *bufD, *bufE, *E2;
    cudaGetSymbolAddress((void**)&X,    g_X);
    cudaGetSymbolAddress((void**)&H1,   g_H1);
    cudaGetSymbolAddress((void**)&W1c,  g_W1c);
    cudaGetSymbolAddress((void**)&W2c,  g_W2c);
    cudaGetSymbolAddress((void**)&W3c,  g_W3c);
    cudaGetSymbolAddress((void**)&W4c,  g_W4c);
    cudaGetSymbolAddress((void**)&W5c,  g_W5c);
    cudaGetSymbolAddress((void**)&bufC, g_bufC);
    cudaGetSymbolAddress((void**)&bufD, g_bufD);
    cudaGetSymbolAddress((void**)&bufE, g_bufE);
    cudaGetSymbolAddress((void**)&E2,   g_E2);

    const int SH = STAGES * STG_BYTES;   // 110592 B
    cudaFuncSetAttribute(gemm_pipe<true,  false>, cudaFuncAttributeMaxDynamicSharedMemorySize, SH);
    cudaFuncSetAttribute(gemm_pipe<false, true >, cudaFuncAttributeMaxDynamicSharedMemorySize, SH);
    cudaFuncSetAttribute(gemm_pipe<false, false>, cudaFuncAttributeMaxDynamicSharedMemorySize, SH);

    // prep: inputs + weights -> tf32 (weights N-padded where needed)
    pack_kernel<<<2048, 256>>>(motions, angles, z);
    cvt_pad<<<4096, 256>>>(l1_w, W1c, 2048, 2368, 2048, 8LL * 2048 * 2368);
    cvt_pad<<<4096, 256>>>(l2_w, W2c, 2368, 2048, 2432, 8LL * 2432 * 2048);
    cvt_pad<<<2048, 256>>>(l3_w, W3c, 2048, 2496, 2048, (long long)2048 * 2496);
    cvt_pad<<<2048, 256>>>(l4_w, W4c, 2368, 2176, 2432, (long long)2432 * 2176);
    cvt_pad<<< 512, 256>>>(l5_w, W5c,  256, 2496,  256, (long long)256 * 2496);

    // L1: H1[e] = tf32(elu(X @ W1[e]^T + b1[e]))   K=2368
    gemm_pipe<true, false><<<dim3(16, 32, 8), 256, SH>>>(
        X, 2368, (size_t)0,
        W1c, (size_t)2048 * 2368,
        l1_b, 2048, nullptr,
        H1, 2048, (size_t)BROWS * 2048,
        2048, 2368);

    // L2: E2[e] = para[e] * elu(H1[e] @ W2[e]^T + b2[e])   K=2048, N=2368(pad 2432)
    gemm_pipe<false, true><<<dim3(19, 32, 8), 256, SH>>>(
        H1, 2048, (size_t)BROWS * 2048,
        W2c, (size_t)2432 * 2048,
        l2_b, 2368, para,
        E2, 2368, (size_t)BROWS * 2368,
        2368, 2048);

    // expert sum -> bufC[:, :2368] (tf32)
    reduce_kernel<<<2048, 256>>>();

    // L3: bufD = tf32(elu(bufC @ W3^T + b3))   K=2496
    gemm_pipe<true, false><<<dim3(16, 32, 1), 256, SH>>>(
        bufC, 2496, (size_t)0, W3c, (size_t)0, l3_b, 0, nullptr,
        bufD, 2176, (size_t)0, 2048, 2496);

    // L4: bufE = tf32(elu(bufD @ W4^T + b4))   K=2176, N=2368(pad 2432)
    gemm_pipe<true, false><<<dim3(19, 32, 1), 256, SH>>>(
        bufD, 2176, (size_t)0, W4c, (size_t)0, l4_b, 0, nullptr,
        bufE, 2496, (size_t)0, 2368, 2176);

    // L5: out = elu(bufE @ W5^T + b5)   K=2496, N=256
    gemm_pipe<false, false><<<dim3(2, 32, 1), 256, SH>>>(
        bufE, 2496, (size_t)0, W5c, (size_t)0, l5_b, 0, nullptr,
        out, 256, (size_t)0, 256, 2496);
}